// round 3
// baseline (speedup 1.0000x reference)
#include <cuda_runtime.h>

#define INV_TAU (1.0f/512.0f)

// Scratch (no cudaMalloc allowed)
__device__ float g_K[8ul*1024*1024];
__device__ float g_Q[8ul*1024*1024];
__device__ float g_O[8ul*1024*1024];
__device__ float g_Z[128ul*1024];

__device__ __forceinline__ unsigned f2t(float f) {
  unsigned u; asm("cvt.rna.tf32.f32 %0, %1;" : "=r"(u) : "f"(f)); return u;
}

__device__ __forceinline__ void mma8(float* c, unsigned a0, unsigned a1,
                                     unsigned a2, unsigned a3,
                                     unsigned b0, unsigned b1) {
  asm("mma.sync.aligned.m16n8k8.row.col.f32.tf32.tf32.f32 "
      "{%0,%1,%2,%3}, {%4,%5,%6,%7}, {%8,%9}, {%0,%1,%2,%3};"
      : "+f"(c[0]), "+f"(c[1]), "+f"(c[2]), "+f"(c[3])
      : "r"(a0), "r"(a1), "r"(a2), "r"(a3), "r"(b0), "r"(b1));
}

// ---------------------------------------------------------------------------
// proj: C[b] = W (1024x1024 row-major) @ X[b] + bias
// 512 threads. Block tile 256(m) x 128(n), k-step 32. Warps 4x4, tile 64x32.
// ---------------------------------------------------------------------------
__global__ __launch_bounds__(512) void proj_mma(
    const float* __restrict__ W, const float* __restrict__ X,
    const float* __restrict__ bias, float* __restrict__ C) {
  extern __shared__ unsigned psm[];
  unsigned* As = psm;             // 256*36 = 9216
  unsigned* Bs = psm + 9216;      // 32*136 = 4352
  const int b = blockIdx.z;
  const float* Xb = X + (size_t)b*1024*1024;
  float* Cb = C + (size_t)b*1024*1024;
  const int row0 = blockIdx.y*256, col0 = blockIdx.x*128;
  const int tid = threadIdx.x, wid = tid>>5, lane = tid&31;
  const int gi = lane>>2, tj = lane&3;
  const int wm = (wid>>2)*64, wn = (wid&3)*32;

  float acc[4][4][4] = {};

  for (int k0 = 0; k0 < 1024; k0 += 32) {
#pragma unroll
    for (int i = 0; i < 4; i++) {
      int idx = tid + i*512;
      int r = idx>>3, k4 = (idx&7)*4;
      float4 v = *(const float4*)&W[(size_t)(row0+r)*1024 + k0 + k4];
      unsigned* p = &As[r*36 + k4];
      p[0]=f2t(v.x); p[1]=f2t(v.y); p[2]=f2t(v.z); p[3]=f2t(v.w);
    }
#pragma unroll
    for (int i = 0; i < 2; i++) {
      int idx = tid + i*512;
      int kk = idx>>5, n4 = (idx&31)*4;
      float4 v = *(const float4*)&Xb[(size_t)(k0+kk)*1024 + col0 + n4];
      unsigned* p = &Bs[kk*136 + n4];
      p[0]=f2t(v.x); p[1]=f2t(v.y); p[2]=f2t(v.z); p[3]=f2t(v.w);
    }
    __syncthreads();
#pragma unroll
    for (int c = 0; c < 4; c++) {
      const int kb = c*8;
      unsigned a[4][4], bb[4][2];
#pragma unroll
      for (int mt = 0; mt < 4; mt++) {
        int m = wm + mt*16;
        a[mt][0] = As[(m+gi)*36 + kb + tj];
        a[mt][1] = As[(m+8+gi)*36 + kb + tj];
        a[mt][2] = As[(m+gi)*36 + kb+4 + tj];
        a[mt][3] = As[(m+8+gi)*36 + kb+4 + tj];
      }
#pragma unroll
      for (int nt = 0; nt < 4; nt++) {
        int n = wn + nt*8 + gi;
        bb[nt][0] = Bs[(kb+tj)*136 + n];
        bb[nt][1] = Bs[(kb+4+tj)*136 + n];
      }
#pragma unroll
      for (int mt = 0; mt < 4; mt++)
#pragma unroll
        for (int nt = 0; nt < 4; nt++)
          mma8(acc[mt][nt], a[mt][0],a[mt][1],a[mt][2],a[mt][3],
               bb[nt][0], bb[nt][1]);
    }
    __syncthreads();
  }
#pragma unroll
  for (int mt = 0; mt < 4; mt++) {
    int r0 = row0 + wm + mt*16 + gi;
    float bv0 = bias[r0], bv1 = bias[r0+8];
#pragma unroll
    for (int nt = 0; nt < 4; nt++) {
      int cc = col0 + wn + nt*8 + 2*tj;
      *(float2*)&Cb[(size_t)r0*1024 + cc] =
          make_float2(acc[mt][nt][0]+bv0, acc[mt][nt][1]+bv0);
      *(float2*)&Cb[(size_t)(r0+8)*1024 + cc] =
          make_float2(acc[mt][nt][2]+bv1, acc[mt][nt][3]+bv1);
    }
  }
}

// ---------------------------------------------------------------------------
// zpass: Z[l] = sum_m exp(S[l,m]/tau), S = K^T Q (contraction over d=64).
// 512 threads. Block: one (bh, 256-l tile); loops m in 128 chunks.
// Warps 4(l) x 4(m), warp tile 64 x 32.
// ---------------------------------------------------------------------------
__global__ __launch_bounds__(512) void zpass_mma(
    const float* __restrict__ Kbuf, const float* __restrict__ Qbuf,
    float* __restrict__ Zbuf) {
  extern __shared__ unsigned zsm[];
  unsigned* Ks = zsm;                         // 64*264 = 16896  [d][l]
  unsigned* Qs = zsm + 16896;                 // 64*136 = 8704   [d][m]
  float* Zpart = (float*)(zsm + 16896+8704);  // 4*256
  const int bh = blockIdx.y, l0 = blockIdx.x*256;
  const size_t base = ((size_t)(bh>>4)*1024 + (size_t)(bh&15)*64)*1024;
  const float* Kh = Kbuf + base;
  const float* Qh = Qbuf + base;
  const int tid = threadIdx.x, wid = tid>>5, lane = tid&31;
  const int gi = lane>>2, tj = lane&3;
  const int wl = (wid>>2)*64, wnn = (wid&3)*32;

#pragma unroll
  for (int i = 0; i < 8; i++) {
    int idx = tid + i*512;
    int r = idx>>6, c4 = (idx&63)*4;
    float4 v = *(const float4*)&Kh[(size_t)r*1024 + l0 + c4];
    unsigned* p = &Ks[r*264 + c4];
    p[0]=f2t(v.x); p[1]=f2t(v.y); p[2]=f2t(v.z); p[3]=f2t(v.w);
  }
  float rs[8] = {};

  for (int m0 = 0; m0 < 1024; m0 += 128) {
    __syncthreads();
#pragma unroll
    for (int i = 0; i < 4; i++) {
      int idx = tid + i*512;
      int r = idx>>5, c4 = (idx&31)*4;
      float4 v = *(const float4*)&Qh[(size_t)r*1024 + m0 + c4];
      unsigned* p = &Qs[r*136 + c4];
      p[0]=f2t(v.x); p[1]=f2t(v.y); p[2]=f2t(v.z); p[3]=f2t(v.w);
    }
    __syncthreads();
    float S[4][4][4] = {};
#pragma unroll
    for (int db = 0; db < 64; db += 8) {
      unsigned a[4][4], bb[4][2];
#pragma unroll
      for (int mt = 0; mt < 4; mt++) {
        int l = wl + mt*16;
        a[mt][0] = Ks[(db+tj)*264 + l + gi];
        a[mt][1] = Ks[(db+tj)*264 + l + 8 + gi];
        a[mt][2] = Ks[(db+4+tj)*264 + l + gi];
        a[mt][3] = Ks[(db+4+tj)*264 + l + 8 + gi];
      }
#pragma unroll
      for (int nt = 0; nt < 4; nt++) {
        int n = wnn + nt*8 + gi;
        bb[nt][0] = Qs[(db+tj)*136 + n];
        bb[nt][1] = Qs[(db+4+tj)*136 + n];
      }
#pragma unroll
      for (int mt = 0; mt < 4; mt++)
#pragma unroll
        for (int nt = 0; nt < 4; nt++)
          mma8(S[mt][nt], a[mt][0],a[mt][1],a[mt][2],a[mt][3],
               bb[nt][0], bb[nt][1]);
    }
#pragma unroll
    for (int mt = 0; mt < 4; mt++)
#pragma unroll
      for (int nt = 0; nt < 4; nt++) {
        rs[2*mt]   += __expf(S[mt][nt][0]*INV_TAU) + __expf(S[mt][nt][1]*INV_TAU);
        rs[2*mt+1] += __expf(S[mt][nt][2]*INV_TAU) + __expf(S[mt][nt][3]*INV_TAU);
      }
  }
#pragma unroll
  for (int i = 0; i < 8; i++) {
    rs[i] += __shfl_xor_sync(0xffffffffu, rs[i], 1);
    rs[i] += __shfl_xor_sync(0xffffffffu, rs[i], 2);
  }
  if (tj == 0) {
#pragma unroll
    for (int mt = 0; mt < 4; mt++) {
      Zpart[(wid&3)*256 + wl + mt*16 + gi]     = rs[2*mt];
      Zpart[(wid&3)*256 + wl + mt*16 + 8 + gi] = rs[2*mt+1];
    }
  }
  __syncthreads();
  if (tid < 256) {
    float z = Zpart[tid] + Zpart[256+tid] + Zpart[512+tid] + Zpart[768+tid];
    Zbuf[(size_t)bh*1024 + l0 + tid] = z;
  }
}

// ---------------------------------------------------------------------------
// opass: O[d,m] = sum_l (x[d,l]/Z[l]) * exp(S[l,m]/tau), flash-style.
// 512 threads. Block: one (bh, 256-m tile); l in 64 chunks.
// Warp grid 2(rows) x 8(m), warp tile 32 x 32. O persistent in C-frags.
// ---------------------------------------------------------------------------
__global__ __launch_bounds__(512) void opass_mma(
    const float* __restrict__ x, const float* __restrict__ Kbuf,
    const float* __restrict__ Qbuf, const float* __restrict__ Zbuf,
    float* __restrict__ Obuf) {
  extern __shared__ unsigned osm[];
  unsigned* Qs  = osm;                          // 64*264 = 16896 [d][m]
  unsigned* Ksc = osm + 16896;                  // 64*72  = 4608  [d][l]
  unsigned* Xs  = osm + 16896+4608;             // 64*68  = 4352  [d][l]
  unsigned* Ps  = osm + 16896+4608+4352;        // 64*264 = 16896 [l][m]
  float* Zr = (float*)(osm + 16896+4608+4352+16896);  // 1024
  const int bh = blockIdx.y, m0 = blockIdx.x*256;
  const size_t base = ((size_t)(bh>>4)*1024 + (size_t)(bh&15)*64)*1024;
  const float* Kh = Kbuf + base;
  const float* Qh = Qbuf + base;
  const float* Xh = x + base;
  const int tid = threadIdx.x, wid = tid>>5, lane = tid&31;
  const int gi = lane>>2, tj = lane&3;
  const int wr = (wid>>3)*32;   // l-rows (GEMM1) / d-rows (GEMM2)
  const int wn = (wid&7)*32;    // m-cols

#pragma unroll
  for (int i = 0; i < 8; i++) {
    int idx = tid + i*512;
    int r = idx>>6, c4 = (idx&63)*4;
    float4 v = *(const float4*)&Qh[(size_t)r*1024 + m0 + c4];
    unsigned* p = &Qs[r*264 + c4];
    p[0]=f2t(v.x); p[1]=f2t(v.y); p[2]=f2t(v.z); p[3]=f2t(v.w);
  }
  {
    float2 z = *(const float2*)&Zbuf[(size_t)bh*1024 + tid*2];
    Zr[tid*2+0] = __frcp_rn(z.x);
    Zr[tid*2+1] = __frcp_rn(z.y);
  }

  float O[2][4][4] = {};

  for (int l0 = 0; l0 < 1024; l0 += 64) {
    __syncthreads();
#pragma unroll
    for (int i = 0; i < 2; i++) {
      int idx = tid + i*512;
      int r = idx>>4, c4 = (idx&15)*4;
      float4 kv = *(const float4*)&Kh[(size_t)r*1024 + l0 + c4];
      unsigned* p = &Ksc[r*72 + c4];
      p[0]=f2t(kv.x); p[1]=f2t(kv.y); p[2]=f2t(kv.z); p[3]=f2t(kv.w);
      float4 xv = *(const float4*)&Xh[(size_t)r*1024 + l0 + c4];
      xv.x *= Zr[l0+c4+0]; xv.y *= Zr[l0+c4+1];
      xv.z *= Zr[l0+c4+2]; xv.w *= Zr[l0+c4+3];
      unsigned* q = &Xs[r*68 + c4];
      q[0]=f2t(xv.x); q[1]=f2t(xv.y); q[2]=f2t(xv.z); q[3]=f2t(xv.w);
    }
    __syncthreads();
    // GEMM1: S chunk = K^T(64l x 64d) @ Q(64d x 256m)
    float S[2][4][4] = {};
#pragma unroll
    for (int db = 0; db < 64; db += 8) {
      unsigned a[2][4], bb[4][2];
#pragma unroll
      for (int mt = 0; mt < 2; mt++) {
        int l = wr + mt*16;
        a[mt][0] = Ksc[(db+tj)*72 + l + gi];
        a[mt][1] = Ksc[(db+tj)*72 + l + 8 + gi];
        a[mt][2] = Ksc[(db+4+tj)*72 + l + gi];
        a[mt][3] = Ksc[(db+4+tj)*72 + l + 8 + gi];
      }
#pragma unroll
      for (int nt = 0; nt < 4; nt++) {
        int n = wn + nt*8 + gi;
        bb[nt][0] = Qs[(db+tj)*264 + n];
        bb[nt][1] = Qs[(db+4+tj)*264 + n];
      }
#pragma unroll
      for (int mt = 0; mt < 2; mt++)
#pragma unroll
        for (int nt = 0; nt < 4; nt++)
          mma8(S[mt][nt], a[mt][0],a[mt][1],a[mt][2],a[mt][3],
               bb[nt][0], bb[nt][1]);
    }
    // exp -> Ps (tf32)
#pragma unroll
    for (int mt = 0; mt < 2; mt++) {
      int l = wr + mt*16 + gi;
#pragma unroll
      for (int nt = 0; nt < 4; nt++) {
        int m = wn + nt*8 + 2*tj;
        Ps[l*264 + m]         = f2t(__expf(S[mt][nt][0]*INV_TAU));
        Ps[l*264 + m + 1]     = f2t(__expf(S[mt][nt][1]*INV_TAU));
        Ps[(l+8)*264 + m]     = f2t(__expf(S[mt][nt][2]*INV_TAU));
        Ps[(l+8)*264 + m + 1] = f2t(__expf(S[mt][nt][3]*INV_TAU));
      }
    }
    __syncthreads();
    // GEMM2: O += X'(64d x 64l) @ P(64l x 256m)
#pragma unroll
    for (int lb = 0; lb < 64; lb += 8) {
      unsigned a[2][4], bb[4][2];
#pragma unroll
      for (int mt = 0; mt < 2; mt++) {
        int d = wr + mt*16;
        a[mt][0] = Xs[(d+gi)*68 + lb + tj];
        a[mt][1] = Xs[(d+8+gi)*68 + lb + tj];
        a[mt][2] = Xs[(d+gi)*68 + lb + 4 + tj];
        a[mt][3] = Xs[(d+8+gi)*68 + lb + 4 + tj];
      }
#pragma unroll
      for (int nt = 0; nt < 4; nt++) {
        int n = wn + nt*8 + gi;
        bb[nt][0] = Ps[(lb+tj)*264 + n];
        bb[nt][1] = Ps[(lb+4+tj)*264 + n];
      }
#pragma unroll
      for (int mt = 0; mt < 2; mt++)
#pragma unroll
        for (int nt = 0; nt < 4; nt++)
          mma8(O[mt][nt], a[mt][0],a[mt][1],a[mt][2],a[mt][3],
               bb[nt][0], bb[nt][1]);
    }
  }
#pragma unroll
  for (int mt = 0; mt < 2; mt++) {
    int d = wr + mt*16 + gi;
#pragma unroll
    for (int nt = 0; nt < 4; nt++) {
      int c = m0 + wn + nt*8 + 2*tj;
      *(float2*)&Obuf[base + (size_t)d*1024 + c] =
          make_float2(O[mt][nt][0], O[mt][nt][1]);
      *(float2*)&Obuf[base + (size_t)(d+8)*1024 + c] =
          make_float2(O[mt][nt][2], O[mt][nt][3]);
    }
  }
}

// ---------------------------------------------------------------------------
extern "C" void kernel_launch(void* const* d_in, const int* in_sizes, int n_in,
                              void* d_out, int out_size) {
  (void)in_sizes; (void)n_in; (void)out_size;
  const float* x  = (const float*)d_in[0];
  const float* y  = (const float*)d_in[1];
  const float* Wk = (const float*)d_in[2];
  const float* bk = (const float*)d_in[3];
  const float* Wq = (const float*)d_in[4];
  const float* bq = (const float*)d_in[5];
  const float* Wp = (const float*)d_in[6];
  const float* bp = (const float*)d_in[7];
  float* out = (float*)d_out;

  float *Kp, *Qp, *Op, *Zp;
  cudaGetSymbolAddress((void**)&Kp, g_K);
  cudaGetSymbolAddress((void**)&Qp, g_Q);
  cudaGetSymbolAddress((void**)&Op, g_O);
  cudaGetSymbolAddress((void**)&Zp, g_Z);

  const int psmem = (9216 + 4352) * 4;                          // 54,272 B
  const int zsmem = (16896 + 8704 + 1024) * 4;                  // 106,496 B
  const int osmem = (16896 + 4608 + 4352 + 16896 + 1024) * 4;   // 175,104 B
  cudaFuncSetAttribute(proj_mma,  cudaFuncAttributeMaxDynamicSharedMemorySize, psmem);
  cudaFuncSetAttribute(zpass_mma, cudaFuncAttributeMaxDynamicSharedMemorySize, zsmem);
  cudaFuncSetAttribute(opass_mma, cudaFuncAttributeMaxDynamicSharedMemorySize, osmem);

  dim3 pg(8, 4, 8);
  proj_mma<<<pg, 512, psmem>>>(Wk, x, bk, Kp);
  proj_mma<<<pg, 512, psmem>>>(Wq, y, bq, Qp);
  zpass_mma<<<dim3(4, 128), 512, zsmem>>>(Kp, Qp, Zp);
  opass_mma<<<dim3(4, 128), 512, osmem>>>(x, Kp, Qp, Zp, Op);
  proj_mma<<<pg, 512, psmem>>>(Wp, Op, bp, out);
}